// round 9
// baseline (speedup 1.0000x reference)
#include <cuda_runtime.h>
#include <cuda_bf16.h>
#include <cstdint>

#define D_MODEL 1024
#define NUM_T   2048
#define BATCH   32

#define PE_ELEMS (NUM_T * D_MODEL)            // 2,097,152
#define PE_VEC8  (PE_ELEMS / 8)               // 262,144 = 2^18
#define DVEC8    (D_MODEL / 8)                // 128

#define BPT     2                             // batches per thread
#define GROUPS  (BATCH / BPT)                 // 16 block-groups

#define LOG2_10000 13.287712379549449f

// 256-bit global accesses (sm_100+), with the policies that won in R8:
// .cg loads (L2-only, skip useless L1), DEFAULT stores (L2 writeback aggregation).
__device__ __forceinline__ void ldg256_cg(const float* p, float* r) {
    asm volatile("ld.global.cg.v8.f32 {%0,%1,%2,%3,%4,%5,%6,%7}, [%8];"
                 : "=f"(r[0]), "=f"(r[1]), "=f"(r[2]), "=f"(r[3]),
                   "=f"(r[4]), "=f"(r[5]), "=f"(r[6]), "=f"(r[7])
                 : "l"(p));
}
__device__ __forceinline__ void stg256(float* p, const float* r) {
    asm volatile("st.global.v8.f32 [%0], {%1,%2,%3,%4,%5,%6,%7,%8};"
                 :: "l"(p),
                    "f"(r[0]), "f"(r[1]), "f"(r[2]), "f"(r[3]),
                    "f"(r[4]), "f"(r[5]), "f"(r[6]), "f"(r[7])
                 : "memory");
}

// Fused PE+add: one thread = one (t, d-vec8) position x 2 batches.
// Flat grid (16384 blocks), exact cover. Combines R7's 256-bit width with
// R8's cache policies — the two independently-measured micro-wins.
__global__ void __launch_bounds__(256) fused_pe_add_kernel(const float* __restrict__ x,
                                                           float* __restrict__ out) {
    const unsigned g   = blockIdx.x & (GROUPS - 1u);      // batch group 0..15
    const unsigned pb  = blockIdx.x >> 4;                 // position block 0..1023
    const unsigned pos = pb * 256u + threadIdx.x;         // 0..PE_VEC8-1

    const int t  = pos >> 7;                  // timestep 0..2047
    const int i0 = (int)(pos & (DVEC8 - 1u)) * 8;         // first column (even)
    const float ft = (float)t;

    // 10000^(-2*i/D) = 2^(i*k)
    const float k = -2.0f / (float)D_MODEL * LOG2_10000;
    float pe[8];
    #pragma unroll
    for (int j = 0; j < 8; j += 2) {
        pe[j]     = sinf(ft * exp2f((float)(i0 + j)     * k));  // even -> sin
        pe[j + 1] = cosf(ft * exp2f((float)(i0 + j + 1) * k));  // odd  -> cos
    }

    const unsigned base = (pos + g * (unsigned)(BPT * PE_VEC8)) * 8u;  // float index

    float xv[BPT][8];
    #pragma unroll
    for (int b = 0; b < BPT; b++)
        ldg256_cg(x + base + (unsigned)b * (PE_VEC8 * 8u), xv[b]);

    #pragma unroll
    for (int b = 0; b < BPT; b++) {
        float o[8];
        #pragma unroll
        for (int j = 0; j < 8; j++) o[j] = xv[b][j] + pe[j];
        stg256(out + base + (unsigned)b * (PE_VEC8 * 8u), o);
    }
}

extern "C" void kernel_launch(void* const* d_in, const int* in_sizes, int n_in,
                              void* d_out, int out_size) {
    const float* x = (const float*)d_in[0];
    float* out = (float*)d_out;
    // (2^18 / 256) position blocks x 16 groups = 16384 blocks, exact cover
    fused_pe_add_kernel<<<(PE_VEC8 / 256) * GROUPS, 256>>>(x, out);
}

// round 10
// speedup vs baseline: 1.0132x; 1.0132x over previous
#include <cuda_runtime.h>
#include <cuda_bf16.h>
#include <cstdint>

#define D_MODEL 1024
#define NUM_T   2048
#define BATCH   32

#define PE_ELEMS (NUM_T * D_MODEL)            // 2,097,152
#define PE_VEC4  (PE_ELEMS / 4)               // 524,288 = 2^19
#define DVEC     (D_MODEL / 4)                // 256

#define BPT     4                             // batches per thread
#define GROUPS  (BATCH / BPT)                 // 8 block-groups
#define PBLOCKS (PE_VEC4 / 256)               // 2048 position blocks per group

#define LOG2_10000 13.287712379549449f

// Fused PE+add, R8 config (best kernel: 75.6us, DRAM 81.2%) with ONE change:
// batch-group taken from the HIGH bits of blockIdx. A concurrent wave
// (~1216 blocks) then covers a single contiguous ~5MB region of one batch
// group instead of 8 interleaved 8MB-strided streams -> better DRAM
// row-buffer locality for the read and write streams.
__global__ void __launch_bounds__(256) fused_pe_add_kernel(const float4* __restrict__ x,
                                                           float4* __restrict__ out) {
    const unsigned pb  = blockIdx.x & (PBLOCKS - 1u);     // position block 0..2047
    const unsigned g   = blockIdx.x >> 11;                // batch group 0..7 (high bits)
    const unsigned pos = pb * 256u + threadIdx.x;         // 0..PE_VEC4-1

    const int t  = pos >> 8;                  // timestep 0..2047
    const int i0 = (int)(pos & (DVEC - 1u)) * 4;          // first column (even)
    const float ft = (float)t;

    // 10000^(-2*i/D) = 2^(i*k)
    const float k = -2.0f / (float)D_MODEL * LOG2_10000;
    float4 pe;
    pe.x = sinf(ft * exp2f((float)(i0 + 0) * k));   // even i -> sin
    pe.y = cosf(ft * exp2f((float)(i0 + 1) * k));   // odd  i -> cos
    pe.z = sinf(ft * exp2f((float)(i0 + 2) * k));
    pe.w = cosf(ft * exp2f((float)(i0 + 3) * k));

    const unsigned base = pos + g * (unsigned)(BPT * PE_VEC4);

    float4 xv[BPT];
    #pragma unroll
    for (int b = 0; b < BPT; b++)
        xv[b] = __ldcg(&x[base + (unsigned)b * PE_VEC4]);   // L2-only load

    #pragma unroll
    for (int b = 0; b < BPT; b++) {
        float4 o;
        o.x = xv[b].x + pe.x;
        o.y = xv[b].y + pe.y;
        o.z = xv[b].z + pe.z;
        o.w = xv[b].w + pe.w;
        out[base + (unsigned)b * PE_VEC4] = o;              // default store policy
    }
}

extern "C" void kernel_launch(void* const* d_in, const int* in_sizes, int n_in,
                              void* d_out, int out_size) {
    const float4* x = (const float4*)d_in[0];
    float4* out = (float4*)d_out;
    // 2048 position blocks x 8 groups = 16384 blocks, exact cover
    fused_pe_add_kernel<<<PBLOCKS * GROUPS, 256>>>(x, out);
}

// round 11
// speedup vs baseline: 1.0207x; 1.0074x over previous
#include <cuda_runtime.h>
#include <cuda_bf16.h>
#include <cstdint>

#define D_MODEL 1024
#define NUM_T   2048
#define BATCH   32

#define PE_VEC4  (NUM_T * D_MODEL / 4)        // 524,288 vec4 per batch
#define DVEC     (D_MODEL / 4)                // 256
#define TPT      4                            // timesteps per thread
#define BLK_PER_BATCH ((NUM_T / TPT))         // 512 blocks per batch

#define LOG2_10000 13.287712379549449f

// Fused PE+add, fully contiguous streaming. One thread = one dvec x 4
// consecutive timesteps in ONE batch. A block covers a contiguous 16KB tile;
// consecutive blocks cover consecutive tiles -> each wave sweeps a single
// contiguous ~19MB region (stream count 4 -> 1 vs R10). PE for t0..t0+3 via
// angle-addition rotation (4 exp2 + 8 sincos + 16 FMA per thread).
__global__ void __launch_bounds__(256) fused_pe_add_kernel(const float4* __restrict__ x,
                                                           float4* __restrict__ out) {
    const unsigned b  = blockIdx.x >> 9;                  // batch 0..31 (high bits)
    const unsigned tb = blockIdx.x & (BLK_PER_BATCH - 1u);// t-chunk 0..511
    const unsigned t0 = tb * TPT;                         // first timestep
    const unsigned dvec = threadIdx.x;                    // 0..255
    const int i0 = (int)dvec * 4;                         // first column (even)

    // inv_m = 10000^(-2*(i0+m)/D) = 2^((i0+m)*kk)
    const float kk = -2.0f / (float)D_MODEL * LOG2_10000;
    const float ft0 = (float)t0;

    float s[4], c[4], sd[4], cd[4];
    #pragma unroll
    for (int m = 0; m < 4; m++) {
        float inv = exp2f((float)(i0 + m) * kk);
        sincosf(ft0 * inv, &s[m], &c[m]);   // angle at t0 (exact)
        sincosf(inv, &sd[m], &cd[m]);       // per-timestep rotation
    }

    const unsigned base = b * (unsigned)PE_VEC4 + t0 * DVEC + dvec;

    // Load all 4 timesteps first (MLP=4, L2-only).
    float4 xv[TPT];
    #pragma unroll
    for (int j = 0; j < TPT; j++)
        xv[j] = __ldcg(&x[base + (unsigned)j * DVEC]);

    #pragma unroll
    for (int j = 0; j < TPT; j++) {
        float4 o;
        o.x = xv[j].x + s[0];   // even i -> sin
        o.y = xv[j].y + c[1];   // odd  i -> cos
        o.z = xv[j].z + s[2];
        o.w = xv[j].w + c[3];
        out[base + (unsigned)j * DVEC] = o;   // default store policy

        // rotate all 4 angles by one timestep
        #pragma unroll
        for (int m = 0; m < 4; m++) {
            float s2 = fmaf(s[m], cd[m],  c[m] * sd[m]);
            float c2 = fmaf(c[m], cd[m], -s[m] * sd[m]);
            s[m] = s2; c[m] = c2;
        }
    }
}

extern "C" void kernel_launch(void* const* d_in, const int* in_sizes, int n_in,
                              void* d_out, int out_size) {
    const float4* x = (const float4*)d_in[0];
    float4* out = (float4*)d_out;
    // 32 batches x 512 t-chunks = 16384 blocks x 256 threads, exact cover
    fused_pe_add_kernel<<<BATCH * BLK_PER_BATCH, 256>>>(x, out);
}